// round 14
// baseline (speedup 1.0000x reference)
#include <cuda_runtime.h>
#include <math.h>

#define T_STEPS 256
#define BATCH   2048
#define DIN     128
#define NQ      16
#define NC      64   // 4 gates * 16 qubits

// 134 MB scratch for the precomputed x-part of the pre-activations.
// zx[t*BATCH*NC + b*NC + c] = sum_{d<128} x[t,b,d] * W[c,d]
__device__ float g_zx[(size_t)T_STEPS * BATCH * NC];

// ---------------------------------------------------------------------------
// Packed fp32x2 helpers (sm_100+ PTX; ptxas will not auto-fuse these)
// ---------------------------------------------------------------------------
__device__ __forceinline__ unsigned long long ffma2(
    unsigned long long a, unsigned long long b, unsigned long long c) {
    unsigned long long d;
    asm("fma.rn.f32x2 %0, %1, %2, %3;" : "=l"(d) : "l"(a), "l"(b), "l"(c));
    return d;
}
__device__ __forceinline__ unsigned long long dup2(float x) {
    unsigned long long d;
    asm("mov.b64 %0, {%1, %1};" : "=l"(d) : "f"(x));
    return d;
}
__device__ __forceinline__ float2 unpack2(unsigned long long v) {
    float2 r;
    asm("mov.b64 {%0, %1}, %2;" : "=f"(r.x), "=f"(r.y) : "l"(v));
    return r;
}

// ---------------------------------------------------------------------------
// Kernel A: GEMM. M = T*B = 524288 rows, N = 64, K = 128 (2 chunks of 64).
// Both tiles stored k-major in smem: inner loop = 2x LDS.128 + 8 FFMA2.
// Thread computes a 4x4 register tile as 4x2 packed f32x2.
// ---------------------------------------------------------------------------
__global__ __launch_bounds__(256) void qlstm_gemm_x(
    const float* __restrict__ X,   // [M, 128]
    const float* __restrict__ W)   // [64, 144] (only d<128 used here)
{
    __shared__ float Xt[64][68];   // [k][row]
    __shared__ float Wt[64][68];   // [k][col]

    const int tid = threadIdx.x;
    const int tx = tid & 15;        // col group (4 cols -> 2 packed pairs)
    const int ty = tid >> 4;        // row group (4 rows)
    const size_t row0 = (size_t)blockIdx.x * 64;

    // loader mapping: 4 threads per row/col along k
    const int lrow = tid >> 2;            // 0..63
    const int lkq  = (tid & 3) * 4;       // 0,4,8,12

    unsigned long long acc[4][2];
#pragma unroll
    for (int r = 0; r < 4; r++) { acc[r][0] = 0ull; acc[r][1] = 0ull; }

#pragma unroll
    for (int kc = 0; kc < 2; kc++) {
        // --- load X tile k-major: Xt[k][row] ---
        {
            const float* xp = &X[(row0 + lrow) * DIN + kc * 64];
#pragma unroll
            for (int i = 0; i < 4; i++) {
                int k4 = lkq + i * 16;
                float4 v = *reinterpret_cast<const float4*>(xp + k4);
                Xt[k4 + 0][lrow] = v.x;
                Xt[k4 + 1][lrow] = v.y;
                Xt[k4 + 2][lrow] = v.z;
                Xt[k4 + 3][lrow] = v.w;
            }
        }
        // --- load W tile k-major: Wt[k][col] ---
        {
            const float* wp = &W[lrow * 144 + kc * 64];
#pragma unroll
            for (int i = 0; i < 4; i++) {
                int k4 = lkq + i * 16;
                float4 v = *reinterpret_cast<const float4*>(wp + k4);
                Wt[k4 + 0][lrow] = v.x;
                Wt[k4 + 1][lrow] = v.y;
                Wt[k4 + 2][lrow] = v.z;
                Wt[k4 + 3][lrow] = v.w;
            }
        }
        __syncthreads();

#pragma unroll 16
        for (int k = 0; k < 64; k++) {
            ulonglong2 bb = *reinterpret_cast<ulonglong2*>(&Wt[k][tx * 4]);
            float4 av = *reinterpret_cast<float4*>(&Xt[k][ty * 4]);
            unsigned long long a0 = dup2(av.x);
            unsigned long long a1 = dup2(av.y);
            unsigned long long a2 = dup2(av.z);
            unsigned long long a3 = dup2(av.w);
            acc[0][0] = ffma2(a0, bb.x, acc[0][0]);
            acc[0][1] = ffma2(a0, bb.y, acc[0][1]);
            acc[1][0] = ffma2(a1, bb.x, acc[1][0]);
            acc[1][1] = ffma2(a1, bb.y, acc[1][1]);
            acc[2][0] = ffma2(a2, bb.x, acc[2][0]);
            acc[2][1] = ffma2(a2, bb.y, acc[2][1]);
            acc[3][0] = ffma2(a3, bb.x, acc[3][0]);
            acc[3][1] = ffma2(a3, bb.y, acc[3][1]);
        }
        __syncthreads();
    }

    // --- store 4x4 tile, float4 per row ---
#pragma unroll
    for (int r = 0; r < 4; r++) {
        float2 lo = unpack2(acc[r][0]);
        float2 hi = unpack2(acc[r][1]);
        float4 v = make_float4(lo.x, lo.y, hi.x, hi.y);
        *reinterpret_cast<float4*>(
            &g_zx[(row0 + ty * 4 + r) * NC + tx * 4]) = v;
    }
}

// ---------------------------------------------------------------------------
// Fast transcendentals (args bounded; abs errors ~1e-6, fine vs 1e-3 budget)
// ---------------------------------------------------------------------------
__device__ __forceinline__ float fsig(float x) {
    return __fdividef(1.0f, 1.0f + __expf(-x));
}
__device__ __forceinline__ float ftanh(float x) {
    float t = __expf(-2.0f * fabsf(x));
    float r = __fdividef(1.0f - t, 1.0f + t);
    return copysignf(r, x);
}

// ---------------------------------------------------------------------------
// Kernel B: sequential recurrence. ONE WARP PER BLOCK (load balance: 2048
// blocks spread 13-14 per SM uniformly instead of 8-vs-16 warp SMs).
// Lanes 0-15  : gates 0 (forget) and 1 (input), qubit n = lane
// Lanes 16-31 : gates 2 (update) and 3 (output), qubit n = lane-16
// Both half-warps maintain identical copies of h[n], c[n] at lane n.
// ---------------------------------------------------------------------------
__global__ __launch_bounds__(32) void qlstm_recur(
    const float* __restrict__ W,      // [4,16,144]
    const float* __restrict__ bias,   // [4,16]
    const float* __restrict__ theta,  // [4,16]
    float* __restrict__ out)          // outputs [T,B,16] ++ hx [B,16] ++ cx [B,16]
{
    const int gw   = blockIdx.x;          // batch row
    const int lane = threadIdx.x;

    const int half = lane >> 4;
    const int n    = lane & 15;
    const int cA   = 32 * half + n;      // column of gate 2*half
    const int cB   = cA + 16;            // column of gate 2*half+1

    // recurrent weights for this lane's two (gate, qubit) outputs
    float whA[16], whB[16];
#pragma unroll
    for (int j = 0; j < 16; j++) {
        whA[j] = W[cA * 144 + 128 + j];
        whB[j] = W[cB * 144 + 128 + j];
    }
    const float ctA = bias[cA] + theta[cA];
    const float ctB = bias[cB] + theta[cB];

    float h = 0.f, c = 0.f;

    const float* zp = g_zx + (size_t)gw * NC;
    const size_t zstride = (size_t)BATCH * NC;

    // prefetch step 0
    float z0n = zp[cA];
    float z1n = zp[cB];

    float* outp = out + (size_t)gw * 16 + n;

    for (int t = 0; t < T_STEPS; t++) {
        float a0 = z0n + ctA;
        float a1 = z1n + ctB;
        // prefetch next step's pre-activations
        if (t + 1 < T_STEPS) {
            const float* q = zp + (size_t)(t + 1) * zstride;
            z0n = q[cA];
            z1n = q[cB];
        }

        // recurrent contribution h . Wh; two accumulator chains per gate
        float b0 = 0.f, b1 = 0.f;
#pragma unroll
        for (int j = 0; j < 16; j += 2) {
            float hj  = __shfl_sync(0xffffffffu, h, j, 16);
            float hj1 = __shfl_sync(0xffffffffu, h, j + 1, 16);
            a0 = fmaf(hj,  whA[j],     a0);
            b0 = fmaf(hj1, whA[j + 1], b0);
            a1 = fmaf(hj,  whB[j],     a1);
            b1 = fmaf(hj1, whB[j + 1], b1);
        }
        a0 += b0;
        a1 += b1;

        a0 = __cosf(a0);
        a1 = __cosf(a1);

        // inclusive prefix product (cumprod over qubits) within each half-warp
#pragma unroll
        for (int d = 1; d < 16; d <<= 1) {
            float p0 = __shfl_up_sync(0xffffffffu, a0, d, 16);
            float p1 = __shfl_up_sync(0xffffffffu, a1, d, 16);
            if (n >= d) { a0 *= p0; a1 *= p1; }
        }

        // gate nonlinearities
        float v0, v1;
        if (half == 0) {            // forget, input
            v0 = fsig(a0);
            v1 = fsig(a1);
        } else {                    // update (tanh), output (sigmoid)
            v0 = ftanh(a0);
            v1 = fsig(a1);
        }

        // exchange with partner half-warp lane
        float pv0 = __shfl_sync(0xffffffffu, v0, lane ^ 16);
        float pv1 = __shfl_sync(0xffffffffu, v1, lane ^ 16);

        float f_, i_, g_, o_;
        if (half == 0) { f_ = v0;  i_ = v1;  g_ = pv0; o_ = pv1; }
        else           { f_ = pv0; i_ = pv1; g_ = v0;  o_ = v1;  }

        c = fmaf(f_, c, i_ * g_);
        h = o_ * ftanh(c);

        if (half == 0) outp[(size_t)t * (BATCH * 16)] = h;
    }

    if (half == 0) {
        const size_t base = (size_t)T_STEPS * BATCH * 16;
        out[base + (size_t)gw * 16 + n] = h;                       // hx
        out[base + (size_t)BATCH * 16 + (size_t)gw * 16 + n] = c;  // cx
    }
}

// ---------------------------------------------------------------------------
extern "C" void kernel_launch(void* const* d_in, const int* in_sizes, int n_in,
                              void* d_out, int out_size) {
    const float* X     = (const float*)d_in[0];   // [T,B,128]
    const float* W     = (const float*)d_in[1];   // [4,16,144]
    const float* bias  = (const float*)d_in[2];   // [4,16]
    const float* theta = (const float*)d_in[3];   // [4,16]
    float* out = (float*)d_out;

    // Kernel A: 524288 rows / 64 per block
    qlstm_gemm_x<<<(T_STEPS * BATCH) / 64, 256>>>(X, W);

    // Kernel B: one warp per batch row, one block per warp (load balance)
    qlstm_recur<<<BATCH, 32>>>(W, bias, theta, out);
}